// round 8
// baseline (speedup 1.0000x reference)
#include <cuda_runtime.h>
#include <cstdint>

#define B_    32
#define IC_   16
#define OC_   16
#define KTOT  65536      // (M-1)*(N-1)
#define E_    131584     // edges
#define VOFF  65792      // M*(N-1)
#define KT    32         // k per tile
#define NBUF  8          // weight pipeline depth (8 x 8KB = 64KB dynamic smem)
#define SLABB (16 * KT * 16)   // slab bytes (16 o x 32 k x float4)
#define NTILE (KTOT / KT)      // 2048

__device__ __forceinline__ unsigned long long pack2(float lo, float hi) {
    unsigned long long r;
    asm("mov.b64 %0, {%1, %2};" : "=l"(r) : "f"(lo), "f"(hi));
    return r;
}
__device__ __forceinline__ void fma2(unsigned long long &acc,
                                     unsigned long long a, unsigned long long b) {
    asm("fma.rn.f32x2 %0, %1, %2, %0;" : "+l"(acc) : "l"(a), "l"(b));
}
__device__ __forceinline__ float2 unpack2(unsigned long long v) {
    float2 f;
    asm("mov.b64 {%0, %1}, %2;" : "=f"(f.x), "=f"(f.y) : "l"(v));
    return f;
}
__device__ __forceinline__ void cp_async16(unsigned dst, const void* src) {
    asm volatile("cp.async.cg.shared.global [%0], [%1], 16;\n"
                 :: "r"(dst), "l"(src) : "memory");
}
__device__ __forceinline__ void cp_commit() {
    asm volatile("cp.async.commit_group;\n" ::: "memory");
}
template<int N>
__device__ __forceinline__ void cp_wait() {
    asm volatile("cp.async.wait_group %0;\n" :: "n"(N) : "memory");
}
__device__ __forceinline__ void bar_named(int id) {
    asm volatile("bar.sync %0, 256;" :: "r"(id) : "memory");
}

// Persistent CTAs, 512 threads, walking k-tiles with stride gridDim.
// Warp y stages slab row y; rows 0..7 are consumed only by warps 0..7 (oh=0),
// rows 8..15 only by warps 8..15 -> the two oh-halves are independent barrier
// domains (named barriers), each consuming 2 ic per barrier.
__global__ __launch_bounds__(512, 1)
void edges_kernel(const float* __restrict__ x,
                  const float4* __restrict__ w4,
                  const float* __restrict__ bias,
                  float* __restrict__ out)
{
    extern __shared__ float4 sw[];   // NBUF slabs of [o*32 + klocal]

    const int lane = threadIdx.x;
    const int y    = threadIdx.y;
    const int oh   = y >> 3;
    const int bg   = y & 7;
    const int bbase = bg * 4;
    const int gstride = gridDim.x;

    // weight copy: thread tld owns slab slot tld (warp y -> slab row y)
    const int tld = y * 32 + lane;
    const float4* wbase = w4 + (size_t)((tld >> 5) * IC_) * KTOT + (tld & 31);
    const unsigned swd0 = (unsigned)__cvta_generic_to_shared(sw) + tld * 16;
    // fma-side slab base for this thread
    const unsigned swr0 = (unsigned)__cvta_generic_to_shared(sw)
                        + ((oh * 8) * KT + lane) * 16;

    const float* xp[4];
    #pragma unroll
    for (int bb = 0; bb < 4; ++bb)
        xp[bb] = x + (size_t)((bbase + bb) * IC_) * E_;

    const int tile0  = blockIdx.x;
    const int ntiles = (NTILE - tile0 + gstride - 1) / gstride;
    const int mtot   = ntiles * IC_;

    // ---- stage-issue state ----
    int s_ic = 0;
    const float4* s_w = wbase + tile0 * KT;
    int issued = 0;
    #pragma unroll
    for (int s = 0; s < 6; ++s) {            // mtot >= 16, fine
        cp_async16(swd0 + s * SLABB, s_w + (size_t)s_ic * KTOT);
        cp_commit();
        if (++s_ic == IC_) { s_ic = 0; s_w += (size_t)gstride * KT; }
        ++issued;
    }

    // ---- x-gather state ----
    int k0 = tile0 * KT;
    int k  = k0 + lane;
    int c0 = k;
    int c2 = VOFF + (k0 >> 8) * 257 + (k0 & 255) + lane;

    float xf[4][4];
    #pragma unroll
    for (int bb = 0; bb < 4; ++bb) {
        const float* xb = xp[bb];
        xf[bb][0] = __ldg(xb + c0);
        xf[bb][1] = __ldg(xb + c0 + 256);
        xf[bb][2] = __ldg(xb + c2);
        xf[bb][3] = __ldg(xb + c2 + 1);
    }

    int m = 0;
    for (int t = 0; t < ntiles; ++t) {
        // next tile's coords (for the cross-tile x prefetch at step 7)
        const int k0n = k0 + gstride * KT;
        const int c0n = k0n + lane;
        const int c2n = VOFF + (k0n >> 8) * 257 + (k0n & 255) + lane;

        unsigned long long acc[8][4];
        #pragma unroll
        for (int oo = 0; oo < 8; ++oo)
            #pragma unroll
            for (int bb = 0; bb < 4; ++bb) acc[oo][bb] = 0ull;

        #pragma unroll 1
        for (int s = 0; s < 8; ++s, m += 2) {
            // ensure stages m, m+1 landed (up to 4 younger in flight)
            const int pend = issued - (m + 2);
            if (pend >= 4)      cp_wait<4>();
            else if (pend == 3) cp_wait<3>();
            else if (pend == 2) cp_wait<2>();
            else if (pend == 1) cp_wait<1>();
            else                cp_wait<0>();
            bar_named(1 + oh);

            // issue stages m+6, m+7
            #pragma unroll
            for (int u = 0; u < 2; ++u) {
                if (issued < mtot) {
                    cp_async16(swd0 + (issued & (NBUF - 1)) * SLABB,
                               s_w + (size_t)s_ic * KTOT);
                    cp_commit();
                    if (++s_ic == IC_) { s_ic = 0; s_w += (size_t)gstride * KT; }
                    ++issued;
                }
            }

            #pragma unroll
            for (int h = 0; h < 2; ++h) {       // two ic per barrier
                // pack current x
                unsigned long long xA[4], xB[4];
                #pragma unroll
                for (int bb = 0; bb < 4; ++bb) {
                    xA[bb] = pack2(xf[bb][0], xf[bb][1]);
                    xB[bb] = pack2(xf[bb][2], xf[bb][3]);
                }

                // prefetch x for the next stage
                const int icn = 2 * s + 1 + h;   // ic index of next stage
                if (icn < IC_) {
                    const int off = icn * E_;
                    #pragma unroll
                    for (int bb = 0; bb < 4; ++bb) {
                        const float* xb = xp[bb] + off;
                        xf[bb][0] = __ldg(xb + c0);
                        xf[bb][1] = __ldg(xb + c0 + 256);
                        xf[bb][2] = __ldg(xb + c2);
                        xf[bb][3] = __ldg(xb + c2 + 1);
                    }
                } else if (t + 1 < ntiles) {     // next tile, ic = 0
                    #pragma unroll
                    for (int bb = 0; bb < 4; ++bb) {
                        const float* xb = xp[bb];
                        xf[bb][0] = __ldg(xb + c0n);
                        xf[bb][1] = __ldg(xb + c0n + 256);
                        xf[bb][2] = __ldg(xb + c2n);
                        xf[bb][3] = __ldg(xb + c2n + 1);
                    }
                }

                // compute: 8 o x 4 b x 2 fma2
                const unsigned sa = swr0 + ((m + h) & (NBUF - 1)) * SLABB;
                #pragma unroll
                for (int oo = 0; oo < 8; ++oo) {
                    unsigned long long wA, wB;
                    asm("ld.shared.v2.u64 {%0, %1}, [%2];"
                        : "=l"(wA), "=l"(wB) : "r"(sa + oo * (KT * 16)));
                    #pragma unroll
                    for (int bb = 0; bb < 4; ++bb) {
                        fma2(acc[oo][bb], wA, xA[bb]);
                        fma2(acc[oo][bb], wB, xB[bb]);
                    }
                }
            }
        }

        // epilogue for this tile
        #pragma unroll
        for (int oo = 0; oo < 8; ++oo) {
            const int o = oh * 8 + oo;
            const float bo = __ldg(&bias[o]);
            #pragma unroll
            for (int bb = 0; bb < 4; ++bb) {
                float2 v = unpack2(acc[oo][bb]);
                out[(size_t)((bbase + bb) * OC_ + o) * KTOT + k] = v.x + v.y + bo;
            }
        }

        k0 = k0n; k = k0 + lane; c0 = c0n; c2 = c2n;
    }
}

extern "C" void kernel_launch(void* const* d_in, const int* in_sizes, int n_in,
                              void* d_out, int out_size)
{
    const float*  x    = (const float*)d_in[0];
    const float4* w4   = (const float4*)d_in[1];
    const float*  bias = (const float*)d_in[2];
    float*        out  = (float*)d_out;

    cudaFuncSetAttribute(edges_kernel,
                         cudaFuncAttributeMaxDynamicSharedMemorySize,
                         NBUF * SLABB);

    dim3 block(32, 16);
    dim3 grid(148);
    edges_kernel<<<grid, block, NBUF * SLABB>>>(x, w4, bias, out);
}